// round 14
// baseline (speedup 1.0000x reference)
#include <cuda_runtime.h>

#define A_CAP   500000
#define MAXG    64
#define CHUNK   2048
#define NB_MAX  256
#define LIST_CAP 128

// ------------- device scratch (static zero-init; k_post resets at end) ------
__device__ unsigned long long g_best[MAXG];          // (iou_bits<<32)|~anchor_idx
__device__ unsigned int g_codeW[(A_CAP + 3) / 4];    // byte/anchor: (bestg<<2)|cls
__device__ int g_posCnt[NB_MAX], g_negCnt[NB_MAX];
__device__ unsigned g_posList[LIST_CAP], g_negList[LIST_CAP];
__device__ int g_done1, g_done2;

// ---------- rare per-gt record update (guarded, ~5% warp entry) -------------
__device__ __forceinline__ void rare_update(
    unsigned long long* s_best, float2* s_at,
    int g, float in, float S, float area, int i)
{
    float den = S - in;                         // (sa+area)-in : reference order
    float iou = in / den;                       // IEEE div.rn, matches reference
    unsigned ib = __float_as_uint(iou);
    unsigned hib = ((volatile unsigned*)&s_best[g])[1];
    if (ib >= hib) {                            // >= : tie -> smaller idx can win
        atomicMax(&s_best[g], ((unsigned long long)ib << 32) | ~(unsigned)i);
        // thr: any anchor with iou' >= record has inter' > record*area*0.999999
        ((volatile float*)&s_at[g])[1] =
            __fmul_rn(__fmul_rn(iou, area), 0.999999f);
    }
}

// ---------------- K1: IoU + per-anchor argmax + per-gt argmax ----------------
// one anchor PAIR per thread; grid = 977; (256,7) -> 36 regs -> SINGLE WAVE
__global__ void __launch_bounds__(256, 7) k_iou(
    const float4* __restrict__ anchors, const float4* __restrict__ gts,
    int A, int G)
{
    __shared__ float4 s_gt[MAXG];
    __shared__ float2 s_at[MAXG];               // (area, dynamic record threshold)
    __shared__ unsigned long long s_best[MAXG];

    int t = threadIdx.x;
    if (t < MAXG) {
        if (t < G) {
            float4 g = gts[t];
            s_gt[t] = g;
            s_at[t] = make_float2(__fmul_rn(g.z - g.x, g.w - g.y), 0.0f);
        } else {                                 // sentinel: never overlaps
            s_gt[t] = make_float4(-4e8f, -4e8f, -4e8f, -4e8f);
            s_at[t] = make_float2(1.0f, 3e38f);
        }
        s_best[t] = 0ull;
    }
    __syncthreads();

    int i0 = (blockIdx.x * 256 + t) * 2;
    int i1 = i0 + 1;
    float4 a0 = (i0 < A) ? anchors[i0] : make_float4(-3e8f,-3e8f,-3e8f,-3e8f);
    float4 a1 = (i1 < A) ? anchors[i1] : make_float4(-3e8f,-3e8f,-3e8f,-3e8f);
    float sa0 = __fmul_rn(a0.z - a0.x, a0.w - a0.y);
    float sa1 = __fmul_rn(a1.z - a1.x, a1.w - a1.y);
    // running best: iou = bi/(bS-bi); compare via in*bS' > bi*S'
    // (in/(S-in) ordering == in*S' ordering: the in*in' terms cancel exactly)
    float bi0 = 0.f, bS0 = 1.f, bi1 = 0.f, bS1 = 1.f;
    int bg0 = 0, bg1 = 0;

    #pragma unroll 8
    for (int g = 0; g < MAXG; g++) {
        float4 gt = s_gt[g];
        float2 at = s_at[g];
        float w0 = fminf(a0.z, gt.z) - fmaxf(a0.x, gt.x);
        float h0 = fminf(a0.w, gt.w) - fmaxf(a0.y, gt.y);
        float in0 = __fmul_rn(fmaxf(w0, 0.f), fmaxf(h0, 0.f));
        float w1 = fminf(a1.z, gt.z) - fmaxf(a1.x, gt.x);
        float h1 = fminf(a1.w, gt.w) - fmaxf(a1.y, gt.y);
        float in1 = __fmul_rn(fmaxf(w1, 0.f), fmaxf(h1, 0.f));
        float S0 = sa0 + at.x;                   // den recomputed only when needed
        float S1 = sa1 + at.x;
        bool u0 = __fmul_rn(in0, bS0) > __fmul_rn(bi0, S0);
        bool u1 = __fmul_rn(in1, bS1) > __fmul_rn(bi1, S1);
        bi0 = u0 ? in0 : bi0;  bS0 = u0 ? S0 : bS0;  bg0 = u0 ? g : bg0;
        bi1 = u1 ? in1 : bi1;  bS1 = u1 ? S1 : bS1;  bg1 = u1 ? g : bg1;
        if (in0 > at.y) rare_update(s_best, s_at, g, in0, S0, at.x, i0);
        if (in1 > at.y) rare_update(s_best, s_at, g, in1, S1, at.x, i1);
    }

    // per-anchor max IoU with reference rounding: den = (sa + area[bg]) - bi
    float den0 = (sa0 + s_at[bg0].x) - bi0;
    float den1 = (sa1 + s_at[bg1].x) - bi1;
    float iou0 = bi0 / den0;                     // one IEEE div per anchor
    float iou1 = bi1 / den1;
    int c0 = (iou0 > 0.5f) ? 2 : ((iou0 < 0.3f) ? 0 : 1);
    int c1 = (iou1 > 0.5f) ? 2 : ((iou1 < 0.3f) ? 0 : 1);
    if (i0 >= A) c0 = 1;                         // padding -> ignore class
    if (i1 >= A) c1 = 1;
    if (i0 < A) {
        unsigned short pk = (unsigned short)(((bg0 << 2) | c0) |
                                             (((bg1 << 2) | c1) << 8));
        ((unsigned short*)g_codeW)[i0 >> 1] = pk;   // coalesced 2-byte store
    }

    __syncthreads();
    if (t < G) {
        unsigned long long v = s_best[t];
        if (v) atomicMax(&g_best[t], v);
    }
}

// ------- K2 (fused): classify+count -> grid sync -> scatter -> loss ---------
__global__ void __launch_bounds__(256) k_post(
    const float* __restrict__ score, const float4* __restrict__ regp,
    const float4* __restrict__ anchors, const float4* __restrict__ gts,
    float* __restrict__ out, int out_size, int A, int G, int nb)
{
    __shared__ unsigned s_mask[CHUNK / 32];
    __shared__ int sp[256], sn[256];
    __shared__ int s_b0, s_b1, s_flag;
    int t = threadIdx.x, bid = blockIdx.x;
    int base = bid * CHUNK;

    // ---- phase 0: forced gt-argmax bitmap for this block's chunk ----
    if (t < CHUNK / 32) s_mask[t] = 0u;
    __syncthreads();
    if (t < G) {
        unsigned long long key = g_best[t];
        // key==0 (gt overlaps nothing) -> reference argmax = anchor 0
        unsigned idx = key ? ~(unsigned)(key & 0xffffffffull) : 0u;
        if (idx < (unsigned)A && (int)idx >= base && (int)idx < base + CHUNK) {
            unsigned off = idx - base;
            atomicOr(&s_mask[off >> 5], 1u << (off & 31));
        }
    }
    __syncthreads();

    // ---- phase 1: classify 8 anchors/thread (kept in regs), count ----
    unsigned char cl[8];
    int pc = 0, nc = 0;
    #pragma unroll
    for (int wj = 0; wj < 2; wj++) {
        int wi = (base >> 2) + t * 2 + wj;
        int ia = wi * 4;
        unsigned wv = (ia < A) ? g_codeW[wi] : 0x01010101u;  // pad: ignore class
        unsigned off = (unsigned)(ia - base);
        unsigned fm = (ia < A) ? ((s_mask[off >> 5] >> (off & 31)) & 0xFu) : 0u;
        #pragma unroll
        for (int b = 0; b < 4; b++) {
            int code = (wv >> (8 * b)) & 255;
            int cls = code & 3;
            if (ia + b >= A) cls = 1;
            if ((fm >> b) & 1) cls = 3;
            cl[wj * 4 + b] = (unsigned char)((code & ~3) | cls);
            pc += (cls >= 2);
            nc += (cls == 0);
        }
    }
    sp[t] = pc; sn[t] = nc;
    __syncthreads();
    for (int s = 128; s > 0; s >>= 1) {
        if (t < s) { sp[t] += sp[t + s]; sn[t] += sn[t + s]; }
        __syncthreads();
    }
    if (t == 0) {
        g_posCnt[bid] = sp[0];
        g_negCnt[bid] = sn[0];
        __threadfence();
        atomicAdd(&g_done1, 1);
    }

    // ---- grid sync 1: wait for all counts ----
    if (t == 0) {
        while (atomicAdd(&g_done1, 0) < nb) __nanosleep(64);
    }
    __syncthreads();
    __threadfence();

    // ---- phase 2: block prefix over earlier blocks, then ordered scatter ----
    sp[t] = (t < bid) ? g_posCnt[t] : 0;
    sn[t] = (t < bid) ? g_negCnt[t] : 0;
    __syncthreads();
    for (int s = 128; s > 0; s >>= 1) {
        if (t < s) { sp[t] += sp[t + s]; sn[t] += sn[t + s]; }
        __syncthreads();
    }
    if (t == 0) { s_b0 = sp[0]; s_b1 = sn[0]; }
    __syncthreads();
    int posBase = s_b0, negBase = s_b1;

    if (posBase < LIST_CAP || negBase < LIST_CAP) {
        __syncthreads();
        sp[t] = pc; sn[t] = nc;       // intra-block inclusive scan
        __syncthreads();
        for (int off = 1; off < 256; off <<= 1) {
            int vp = (t >= off) ? sp[t - off] : 0;
            int vn = (t >= off) ? sn[t - off] : 0;
            __syncthreads();
            sp[t] += vp; sn[t] += vn;
            __syncthreads();
        }
        int pr = posBase + sp[t] - pc;
        int nr = negBase + sn[t] - nc;
        #pragma unroll
        for (int j = 0; j < 8; j++) {
            int i = base + t * 8 + j;
            int cls = cl[j] & 3;
            unsigned packed = ((unsigned)i << 8) | cl[j];
            if (cls >= 2)      { if (pr < LIST_CAP) g_posList[pr] = packed; pr++; }
            else if (cls == 0) { if (nr < LIST_CAP) g_negList[nr] = packed; nr++; }
        }
    }
    __syncthreads();

    // ---- grid sync 2: last block to finish scatter runs the loss ----
    if (t == 0) {
        __threadfence();
        int old = atomicAdd(&g_done2, 1);
        s_flag = (old == nb - 1);
    }
    __syncthreads();
    if (!s_flag) return;
    __threadfence();

    // ---- phase 3: totals ----
    sp[t] = (t < nb) ? g_posCnt[t] : 0;
    sn[t] = (t < nb) ? g_negCnt[t] : 0;
    __syncthreads();
    for (int s = 128; s > 0; s >>= 1) {
        if (t < s) { sp[t] += sp[t + s]; sn[t] += sn[t + s]; }
        __syncthreads();
    }
    if (t == 0) { s_b0 = sp[0]; s_b1 = sn[0]; }
    __syncthreads();
    int posTotal = s_b0, negTotal = s_b1;

    bool bug = (posTotal >= LIST_CAP);
    int P = bug ? LIST_CAP : posTotal;                 // P <= 128
    int Nn = min(bug ? LIST_CAP : P, negTotal);        // Nn <= 128

    float cls = 0.f, reg = 0.f, ncls = 0.f;

    if (t < LIST_CAP) {
        // threads 0..127: one positive item each
        if (t < P) {
            unsigned e = g_posList[t];
            int idx = (int)(e >> 8);
            int gidx = (e >> 2) & 63;
            float4 a = anchors[idx];
            float lse, x0;
            if (bug) {
                float m = fmaxf(fmaxf(a.x, a.y), fmaxf(a.z, a.w));
                float s = expf(a.x-m) + expf(a.y-m) + expf(a.z-m) + expf(a.w-m);
                lse = m + logf(s); x0 = a.x;
            } else {
                float s0 = score[2 * idx], s1 = score[2 * idx + 1];
                float m = fmaxf(s0, s1);
                lse = m + logf(expf(s0 - m) + expf(s1 - m)); x0 = s0;
            }
            cls = lse - x0;

            float4 g = gts[gidx];
            float aw = a.z - a.x, ah = a.w - a.y;
            float acx = a.x + aw * 0.5f, acy = a.y + ah * 0.5f;
            float gw = g.z - g.x, gh = g.w - g.y;
            float gcx = g.x + gw * 0.5f, gcy = g.y + gh * 0.5f;
            float tx = (gcx - acx) / aw;
            float ty = (gcy - acy) / ah;
            float tw = logf(gw / aw);
            float th = logf(gh / ah);
            float4 r = regp[idx];
            float d, ad;
            d = r.x - tx; ad = fabsf(d); reg += (ad < 1.f) ? 0.5f*d*d : ad - 0.5f;
            d = r.y - ty; ad = fabsf(d); reg += (ad < 1.f) ? 0.5f*d*d : ad - 0.5f;
            d = r.z - tw; ad = fabsf(d); reg += (ad < 1.f) ? 0.5f*d*d : ad - 0.5f;
            d = r.w - th; ad = fabsf(d); reg += (ad < 1.f) ? 0.5f*d*d : ad - 0.5f;
        }
    } else {
        // threads 128..255: one negative item each
        int j = t - LIST_CAP;
        if (j < Nn) {
            int idx = (int)(g_negList[j] >> 8);
            float s0 = score[2 * idx], s1 = score[2 * idx + 1];
            float m = fmaxf(s0, s1);
            float lse = m + logf(expf(s0 - m) + expf(s1 - m));
            ncls = lse - s1;
        }
    }

    __shared__ float fc[256], fr[256], fn[256];
    fc[t] = cls; fr[t] = reg; fn[t] = ncls;
    __syncthreads();
    for (int s = 128; s > 0; s >>= 1) {
        if (t < s) { fc[t] += fc[t+s]; fr[t] += fr[t+s]; fn[t] += fn[t+s]; }
        __syncthreads();
    }
    if (t == 0) {
        float pcl = (P  > 0) ? fc[0] / (float)P  : 0.f;
        float rg  = (P  > 0) ? fr[0] / (float)P  : 0.f;
        float ncl = (Nn > 0) ? fn[0] / (float)Nn : 0.f;
        float v = pcl + rg + ncl;
        for (int o = 0; o < out_size; o++) out[o] = v;
        g_done1 = 0;
        g_done2 = 0;
    }
    if (t < MAXG) g_best[t] = 0ull;   // clean state for next graph replay
}

// ---------------- host launcher ---------------------------------------------
extern "C" void kernel_launch(void* const* d_in, const int* in_sizes, int n_in,
                              void* d_out, int out_size) {
    const float*  score   = (const float*)d_in[0];      // (A,2)
    const float4* regp    = (const float4*)d_in[1];     // (A,4)
    const float4* anchors = (const float4*)d_in[2];     // (A,4)
    const float4* gts     = (const float4*)d_in[3];     // (G,4)
    int A = in_sizes[0] / 2;
    int G = in_sizes[3] / 4;
    if (G > MAXG) G = MAXG;

    int grid1 = (A + 511) / 512;        // 977 blocks; (256,7) -> single wave
    int nb = (A + CHUNK - 1) / CHUNK;   // 245 <= NB_MAX, all blocks co-resident

    k_iou<<<grid1, 256>>>(anchors, gts, A, G);
    k_post<<<nb, 256>>>(score, regp, anchors, gts, (float*)d_out, out_size,
                        A, G, nb);
}

// round 15
// speedup vs baseline: 1.0152x; 1.0152x over previous
#include <cuda_runtime.h>

#define A_CAP   500000
#define MAXG    64
#define K1B     128          // k_iou block size (fine-grained for occupancy)
#define CHUNK   2048
#define NB_MAX  256
#define LIST_CAP 128

// ------------- device scratch (static zero-init; k_post resets at end) ------
__device__ unsigned long long g_best[MAXG];          // (iou_bits<<32)|~anchor_idx
__device__ unsigned int g_codeW[(A_CAP + 3) / 4];    // byte/anchor: (bestg<<2)|cls
__device__ int g_posCnt[NB_MAX], g_negCnt[NB_MAX];
__device__ unsigned g_posList[LIST_CAP], g_negList[LIST_CAP];
__device__ int g_done1, g_done2;

// ---------- rare per-gt record update (guarded, ~5% warp entry) -------------
__device__ __forceinline__ void rare_update(
    unsigned long long* s_best, float2* s_at,
    int g, float in, float den, float area, int i)
{
    float iou = in / den;                       // IEEE div.rn, matches reference
    unsigned ib = __float_as_uint(iou);
    unsigned hib = ((volatile unsigned*)&s_best[g])[1];
    if (ib >= hib) {                            // >= : tie -> smaller idx can win
        atomicMax(&s_best[g], ((unsigned long long)ib << 32) | ~(unsigned)i);
        // thr: any anchor with iou' >= record has inter' > record*area*0.999999
        ((volatile float*)&s_at[g])[1] =
            __fmul_rn(__fmul_rn(iou, area), 0.999999f);
    }
}

// ---------------- K1: IoU + per-anchor argmax + per-gt argmax ----------------
// one anchor PAIR per thread; 128-thread blocks -> 12 blocks/SM, fine tail
__global__ void __launch_bounds__(K1B) k_iou(
    const float4* __restrict__ anchors, const float4* __restrict__ gts,
    int A, int G)
{
    __shared__ float4 s_gt[MAXG];
    __shared__ float2 s_at[MAXG];               // (area, dynamic record threshold)
    __shared__ unsigned long long s_best[MAXG];

    int t = threadIdx.x;
    if (t < MAXG) {
        if (t < G) {
            float4 g = gts[t];
            s_gt[t] = g;
            s_at[t] = make_float2(__fmul_rn(g.z - g.x, g.w - g.y), 0.0f);
        } else {                                 // sentinel: never overlaps
            s_gt[t] = make_float4(-4e8f, -4e8f, -4e8f, -4e8f);
            s_at[t] = make_float2(1.0f, 3e38f);
        }
        s_best[t] = 0ull;
    }
    __syncthreads();

    int i0 = (blockIdx.x * K1B + t) * 2;
    int i1 = i0 + 1;
    float4 a0 = (i0 < A) ? anchors[i0] : make_float4(-3e8f,-3e8f,-3e8f,-3e8f);
    float4 a1 = (i1 < A) ? anchors[i1] : make_float4(-3e8f,-3e8f,-3e8f,-3e8f);
    float sa0 = __fmul_rn(a0.z - a0.x, a0.w - a0.y);
    float sa1 = __fmul_rn(a1.z - a1.x, a1.w - a1.y);
    // running best iou = bi/bd (cross-multiplication; exact tie keeps earlier g)
    float bi0 = 0.f, bd0 = 1.f, bi1 = 0.f, bd1 = 1.f;
    int bg0 = 0, bg1 = 0;

    #pragma unroll 8
    for (int g = 0; g < MAXG; g++) {
        float4 gt = s_gt[g];
        float2 at = s_at[g];
        float w0 = fminf(a0.z, gt.z) - fmaxf(a0.x, gt.x);
        float h0 = fminf(a0.w, gt.w) - fmaxf(a0.y, gt.y);
        float in0 = __fmul_rn(fmaxf(w0, 0.f), fmaxf(h0, 0.f));
        float w1 = fminf(a1.z, gt.z) - fmaxf(a1.x, gt.x);
        float h1 = fminf(a1.w, gt.w) - fmaxf(a1.y, gt.y);
        float in1 = __fmul_rn(fmaxf(w1, 0.f), fmaxf(h1, 0.f));
        float den0 = (sa0 + at.x) - in0;         // adds only, no contraction
        float den1 = (sa1 + at.x) - in1;
        bool u0 = __fmul_rn(in0, bd0) > __fmul_rn(bi0, den0);
        bool u1 = __fmul_rn(in1, bd1) > __fmul_rn(bi1, den1);
        bi0 = u0 ? in0 : bi0;  bd0 = u0 ? den0 : bd0;  bg0 = u0 ? g : bg0;
        bi1 = u1 ? in1 : bi1;  bd1 = u1 ? den1 : bd1;  bg1 = u1 ? g : bg1;
        if (in0 > at.y) rare_update(s_best, s_at, g, in0, den0, at.x, i0);
        if (in1 > at.y) rare_update(s_best, s_at, g, in1, den1, at.x, i1);
    }

    float iou0 = bi0 / bd0;                      // one IEEE div per anchor
    float iou1 = bi1 / bd1;
    int c0 = (iou0 > 0.5f) ? 2 : ((iou0 < 0.3f) ? 0 : 1);
    int c1 = (iou1 > 0.5f) ? 2 : ((iou1 < 0.3f) ? 0 : 1);
    if (i0 >= A) c0 = 1;                         // padding -> ignore class
    if (i1 >= A) c1 = 1;
    if (i0 < A) {
        unsigned short pk = (unsigned short)(((bg0 << 2) | c0) |
                                             (((bg1 << 2) | c1) << 8));
        ((unsigned short*)g_codeW)[i0 >> 1] = pk;   // coalesced 2-byte store
    }

    __syncthreads();
    if (t < G) {
        unsigned long long v = s_best[t];
        if (v) atomicMax(&g_best[t], v);
    }
}

// ------- K2 (fused): classify+count -> grid sync -> scatter -> loss ---------
__global__ void __launch_bounds__(256) k_post(
    const float* __restrict__ score, const float4* __restrict__ regp,
    const float4* __restrict__ anchors, const float4* __restrict__ gts,
    float* __restrict__ out, int out_size, int A, int G, int nb)
{
    __shared__ unsigned s_mask[CHUNK / 32];
    __shared__ int sp[256], sn[256];
    __shared__ int s_b0, s_b1, s_flag;
    int t = threadIdx.x, bid = blockIdx.x;
    int base = bid * CHUNK;

    // ---- phase 0: forced gt-argmax bitmap for this block's chunk ----
    if (t < CHUNK / 32) s_mask[t] = 0u;
    __syncthreads();
    if (t < G) {
        unsigned long long key = g_best[t];
        // key==0 (gt overlaps nothing) -> reference argmax = anchor 0
        unsigned idx = key ? ~(unsigned)(key & 0xffffffffull) : 0u;
        if (idx < (unsigned)A && (int)idx >= base && (int)idx < base + CHUNK) {
            unsigned off = idx - base;
            atomicOr(&s_mask[off >> 5], 1u << (off & 31));
        }
    }
    __syncthreads();

    // ---- phase 1: classify 8 anchors/thread (kept in regs), count ----
    unsigned char cl[8];
    int pc = 0, nc = 0;
    #pragma unroll
    for (int wj = 0; wj < 2; wj++) {
        int wi = (base >> 2) + t * 2 + wj;
        int ia = wi * 4;
        unsigned wv = (ia < A) ? g_codeW[wi] : 0x01010101u;  // pad: ignore class
        unsigned off = (unsigned)(ia - base);
        unsigned fm = (ia < A) ? ((s_mask[off >> 5] >> (off & 31)) & 0xFu) : 0u;
        #pragma unroll
        for (int b = 0; b < 4; b++) {
            int code = (wv >> (8 * b)) & 255;
            int cls = code & 3;
            if (ia + b >= A) cls = 1;
            if ((fm >> b) & 1) cls = 3;
            cl[wj * 4 + b] = (unsigned char)((code & ~3) | cls);
            pc += (cls >= 2);
            nc += (cls == 0);
        }
    }
    sp[t] = pc; sn[t] = nc;
    __syncthreads();
    for (int s = 128; s > 0; s >>= 1) {
        if (t < s) { sp[t] += sp[t + s]; sn[t] += sn[t + s]; }
        __syncthreads();
    }
    if (t == 0) {
        g_posCnt[bid] = sp[0];
        g_negCnt[bid] = sn[0];
        __threadfence();
        atomicAdd(&g_done1, 1);
    }

    // ---- grid sync 1: wait for all counts ----
    if (t == 0) {
        while (atomicAdd(&g_done1, 0) < nb) __nanosleep(64);
    }
    __syncthreads();
    __threadfence();

    // ---- phase 2: block prefix over earlier blocks, then ordered scatter ----
    sp[t] = (t < bid) ? g_posCnt[t] : 0;
    sn[t] = (t < bid) ? g_negCnt[t] : 0;
    __syncthreads();
    for (int s = 128; s > 0; s >>= 1) {
        if (t < s) { sp[t] += sp[t + s]; sn[t] += sn[t + s]; }
        __syncthreads();
    }
    if (t == 0) { s_b0 = sp[0]; s_b1 = sn[0]; }
    __syncthreads();
    int posBase = s_b0, negBase = s_b1;

    if (posBase < LIST_CAP || negBase < LIST_CAP) {
        __syncthreads();
        sp[t] = pc; sn[t] = nc;       // intra-block inclusive scan
        __syncthreads();
        for (int off = 1; off < 256; off <<= 1) {
            int vp = (t >= off) ? sp[t - off] : 0;
            int vn = (t >= off) ? sn[t - off] : 0;
            __syncthreads();
            sp[t] += vp; sn[t] += vn;
            __syncthreads();
        }
        int pr = posBase + sp[t] - pc;
        int nr = negBase + sn[t] - nc;
        #pragma unroll
        for (int j = 0; j < 8; j++) {
            int i = base + t * 8 + j;
            int cls = cl[j] & 3;
            unsigned packed = ((unsigned)i << 8) | cl[j];
            if (cls >= 2)      { if (pr < LIST_CAP) g_posList[pr] = packed; pr++; }
            else if (cls == 0) { if (nr < LIST_CAP) g_negList[nr] = packed; nr++; }
        }
    }
    __syncthreads();

    // ---- grid sync 2: last block to finish scatter runs the loss ----
    if (t == 0) {
        __threadfence();
        int old = atomicAdd(&g_done2, 1);
        s_flag = (old == nb - 1);
    }
    __syncthreads();
    if (!s_flag) return;
    __threadfence();

    // ---- phase 3: totals ----
    sp[t] = (t < nb) ? g_posCnt[t] : 0;
    sn[t] = (t < nb) ? g_negCnt[t] : 0;
    __syncthreads();
    for (int s = 128; s > 0; s >>= 1) {
        if (t < s) { sp[t] += sp[t + s]; sn[t] += sn[t + s]; }
        __syncthreads();
    }
    if (t == 0) { s_b0 = sp[0]; s_b1 = sn[0]; }
    __syncthreads();
    int posTotal = s_b0, negTotal = s_b1;

    bool bug = (posTotal >= LIST_CAP);
    int P = bug ? LIST_CAP : posTotal;                 // P <= 128
    int Nn = min(bug ? LIST_CAP : P, negTotal);        // Nn <= 128

    float cls = 0.f, reg = 0.f, ncls = 0.f;

    if (t < LIST_CAP) {
        // threads 0..127: one positive item each
        if (t < P) {
            unsigned e = g_posList[t];
            int idx = (int)(e >> 8);
            int gidx = (e >> 2) & 63;
            float4 a = anchors[idx];
            float lse, x0;
            if (bug) {
                float m = fmaxf(fmaxf(a.x, a.y), fmaxf(a.z, a.w));
                float s = expf(a.x-m) + expf(a.y-m) + expf(a.z-m) + expf(a.w-m);
                lse = m + logf(s); x0 = a.x;
            } else {
                float s0 = score[2 * idx], s1 = score[2 * idx + 1];
                float m = fmaxf(s0, s1);
                lse = m + logf(expf(s0 - m) + expf(s1 - m)); x0 = s0;
            }
            cls = lse - x0;

            float4 g = gts[gidx];
            float aw = a.z - a.x, ah = a.w - a.y;
            float acx = a.x + aw * 0.5f, acy = a.y + ah * 0.5f;
            float gw = g.z - g.x, gh = g.w - g.y;
            float gcx = g.x + gw * 0.5f, gcy = g.y + gh * 0.5f;
            float tx = (gcx - acx) / aw;
            float ty = (gcy - acy) / ah;
            float tw = logf(gw / aw);
            float th = logf(gh / ah);
            float4 r = regp[idx];
            float d, ad;
            d = r.x - tx; ad = fabsf(d); reg += (ad < 1.f) ? 0.5f*d*d : ad - 0.5f;
            d = r.y - ty; ad = fabsf(d); reg += (ad < 1.f) ? 0.5f*d*d : ad - 0.5f;
            d = r.z - tw; ad = fabsf(d); reg += (ad < 1.f) ? 0.5f*d*d : ad - 0.5f;
            d = r.w - th; ad = fabsf(d); reg += (ad < 1.f) ? 0.5f*d*d : ad - 0.5f;
        }
    } else {
        // threads 128..255: one negative item each
        int j = t - LIST_CAP;
        if (j < Nn) {
            int idx = (int)(g_negList[j] >> 8);
            float s0 = score[2 * idx], s1 = score[2 * idx + 1];
            float m = fmaxf(s0, s1);
            float lse = m + logf(expf(s0 - m) + expf(s1 - m));
            ncls = lse - s1;
        }
    }

    __shared__ float fc[256], fr[256], fn[256];
    fc[t] = cls; fr[t] = reg; fn[t] = ncls;
    __syncthreads();
    for (int s = 128; s > 0; s >>= 1) {
        if (t < s) { fc[t] += fc[t+s]; fr[t] += fr[t+s]; fn[t] += fn[t+s]; }
        __syncthreads();
    }
    if (t == 0) {
        float pcl = (P  > 0) ? fc[0] / (float)P  : 0.f;
        float rg  = (P  > 0) ? fr[0] / (float)P  : 0.f;
        float ncl = (Nn > 0) ? fn[0] / (float)Nn : 0.f;
        float v = pcl + rg + ncl;
        for (int o = 0; o < out_size; o++) out[o] = v;
        g_done1 = 0;
        g_done2 = 0;
    }
    if (t < MAXG) g_best[t] = 0ull;   // clean state for next graph replay
}

// ---------------- host launcher ---------------------------------------------
extern "C" void kernel_launch(void* const* d_in, const int* in_sizes, int n_in,
                              void* d_out, int out_size) {
    const float*  score   = (const float*)d_in[0];      // (A,2)
    const float4* regp    = (const float4*)d_in[1];     // (A,4)
    const float4* anchors = (const float4*)d_in[2];     // (A,4)
    const float4* gts     = (const float4*)d_in[3];     // (G,4)
    int A = in_sizes[0] / 2;
    int G = in_sizes[3] / 4;
    if (G > MAXG) G = MAXG;

    int grid1 = (A + K1B * 2 - 1) / (K1B * 2);  // 1954 fine blocks
    int nb = (A + CHUNK - 1) / CHUNK;           // 245 <= NB_MAX, co-resident

    k_iou<<<grid1, K1B>>>(anchors, gts, A, G);
    k_post<<<nb, 256>>>(score, regp, anchors, gts, (float*)d_out, out_size,
                        A, G, nb);
}

// round 16
// speedup vs baseline: 1.0781x; 1.0620x over previous
#include <cuda_runtime.h>

#define A_CAP   500000
#define MAXG    64
#define CHUNK   2048
#define NB_MAX  256
#define LIST_CAP 128

// ------------- device scratch (static zero-init; k_post resets at end) ------
__device__ unsigned long long g_best[MAXG];          // (iou_bits<<32)|~anchor_idx
__device__ unsigned int g_codeW[(A_CAP + 3) / 4];    // byte/anchor: (bestg<<2)|cls
__device__ int g_posCnt[NB_MAX], g_negCnt[NB_MAX];
__device__ unsigned g_posList[LIST_CAP], g_negList[LIST_CAP];
__device__ int g_done1, g_done2;

// ---------- rare per-gt record update (guarded, ~5% warp entry) -------------
__device__ __forceinline__ void rare_update(
    unsigned long long* s_best, float2* s_at,
    int g, float in, float den, float area, int i)
{
    float iou = in / den;                       // IEEE div.rn, matches reference
    unsigned ib = __float_as_uint(iou);
    unsigned hib = ((volatile unsigned*)&s_best[g])[1];
    if (ib >= hib) {                            // >= : tie -> smaller idx can win
        atomicMax(&s_best[g], ((unsigned long long)ib << 32) | ~(unsigned)i);
        // thr: any anchor with iou' >= record has inter' > record*area*0.999999
        ((volatile float*)&s_at[g])[1] =
            __fmul_rn(__fmul_rn(iou, area), 0.999999f);
    }
}

// ---------------- K1: IoU + per-anchor argmax + per-gt argmax ----------------
// one anchor PAIR per thread; grid = ceil(A/512) = 977; champion config
__global__ void __launch_bounds__(256) k_iou(
    const float4* __restrict__ anchors, const float4* __restrict__ gts,
    int A, int G)
{
    __shared__ float4 s_gt[MAXG];
    __shared__ float2 s_at[MAXG];               // (area, dynamic record threshold)
    __shared__ unsigned long long s_best[MAXG];

    int t = threadIdx.x;
    if (t < MAXG) {
        if (t < G) {
            float4 g = gts[t];
            s_gt[t] = g;
            s_at[t] = make_float2(__fmul_rn(g.z - g.x, g.w - g.y), 0.0f);
        } else {                                 // sentinel: never overlaps
            s_gt[t] = make_float4(-4e8f, -4e8f, -4e8f, -4e8f);
            s_at[t] = make_float2(1.0f, 3e38f);
        }
        s_best[t] = 0ull;
    }
    __syncthreads();

    int i0 = (blockIdx.x * 256 + t) * 2;
    int i1 = i0 + 1;
    float4 a0 = (i0 < A) ? anchors[i0] : make_float4(-3e8f,-3e8f,-3e8f,-3e8f);
    float4 a1 = (i1 < A) ? anchors[i1] : make_float4(-3e8f,-3e8f,-3e8f,-3e8f);
    float sa0 = __fmul_rn(a0.z - a0.x, a0.w - a0.y);
    float sa1 = __fmul_rn(a1.z - a1.x, a1.w - a1.y);
    // running best iou = bi/bd (cross-multiplication; exact tie keeps earlier g)
    float bi0 = 0.f, bd0 = 1.f, bi1 = 0.f, bd1 = 1.f;
    int bg0 = 0, bg1 = 0;

    #pragma unroll 8
    for (int g = 0; g < MAXG; g++) {
        float4 gt = s_gt[g];
        float2 at = s_at[g];
        float w0 = fminf(a0.z, gt.z) - fmaxf(a0.x, gt.x);
        float h0 = fminf(a0.w, gt.w) - fmaxf(a0.y, gt.y);
        float in0 = __fmul_rn(fmaxf(w0, 0.f), fmaxf(h0, 0.f));
        float w1 = fminf(a1.z, gt.z) - fmaxf(a1.x, gt.x);
        float h1 = fminf(a1.w, gt.w) - fmaxf(a1.y, gt.y);
        float in1 = __fmul_rn(fmaxf(w1, 0.f), fmaxf(h1, 0.f));
        float den0 = (sa0 + at.x) - in0;         // adds only, no contraction
        float den1 = (sa1 + at.x) - in1;
        bool u0 = __fmul_rn(in0, bd0) > __fmul_rn(bi0, den0);
        bool u1 = __fmul_rn(in1, bd1) > __fmul_rn(bi1, den1);
        bi0 = u0 ? in0 : bi0;  bd0 = u0 ? den0 : bd0;  bg0 = u0 ? g : bg0;
        bi1 = u1 ? in1 : bi1;  bd1 = u1 ? den1 : bd1;  bg1 = u1 ? g : bg1;
        if (in0 > at.y) rare_update(s_best, s_at, g, in0, den0, at.x, i0);
        if (in1 > at.y) rare_update(s_best, s_at, g, in1, den1, at.x, i1);
    }

    float iou0 = bi0 / bd0;                      // one IEEE div per anchor
    float iou1 = bi1 / bd1;
    int c0 = (iou0 > 0.5f) ? 2 : ((iou0 < 0.3f) ? 0 : 1);
    int c1 = (iou1 > 0.5f) ? 2 : ((iou1 < 0.3f) ? 0 : 1);
    if (i0 >= A) c0 = 1;                         // padding -> ignore class
    if (i1 >= A) c1 = 1;
    if (i0 < A) {
        unsigned short pk = (unsigned short)(((bg0 << 2) | c0) |
                                             (((bg1 << 2) | c1) << 8));
        ((unsigned short*)g_codeW)[i0 >> 1] = pk;   // coalesced 2-byte store
    }

    __syncthreads();
    if (t < G) {
        unsigned long long v = s_best[t];
        if (v) atomicMax(&g_best[t], v);
    }
}

// ------- K2 (fused): classify+count -> grid sync -> scatter -> loss ---------
__global__ void __launch_bounds__(256) k_post(
    const float* __restrict__ score, const float4* __restrict__ regp,
    const float4* __restrict__ anchors, const float4* __restrict__ gts,
    float* __restrict__ out, int out_size, int A, int G, int nb)
{
    __shared__ unsigned s_mask[CHUNK / 32];
    __shared__ int sp[256], sn[256];
    __shared__ int s_b0, s_b1, s_flag;
    int t = threadIdx.x, bid = blockIdx.x;
    int base = bid * CHUNK;

    // ---- phase 0: forced gt-argmax bitmap for this block's chunk ----
    if (t < CHUNK / 32) s_mask[t] = 0u;
    __syncthreads();
    if (t < G) {
        unsigned long long key = g_best[t];
        // key==0 (gt overlaps nothing) -> reference argmax = anchor 0
        unsigned idx = key ? ~(unsigned)(key & 0xffffffffull) : 0u;
        if (idx < (unsigned)A && (int)idx >= base && (int)idx < base + CHUNK) {
            unsigned off = idx - base;
            atomicOr(&s_mask[off >> 5], 1u << (off & 31));
        }
    }
    __syncthreads();

    // ---- phase 1: classify 8 anchors/thread (kept in regs), count ----
    unsigned char cl[8];
    int pc = 0, nc = 0;
    #pragma unroll
    for (int wj = 0; wj < 2; wj++) {
        int wi = (base >> 2) + t * 2 + wj;
        int ia = wi * 4;
        unsigned wv = (ia < A) ? g_codeW[wi] : 0x01010101u;  // pad: ignore class
        unsigned off = (unsigned)(ia - base);
        unsigned fm = (ia < A) ? ((s_mask[off >> 5] >> (off & 31)) & 0xFu) : 0u;
        #pragma unroll
        for (int b = 0; b < 4; b++) {
            int code = (wv >> (8 * b)) & 255;
            int cls = code & 3;
            if (ia + b >= A) cls = 1;
            if ((fm >> b) & 1) cls = 3;
            cl[wj * 4 + b] = (unsigned char)((code & ~3) | cls);
            pc += (cls >= 2);
            nc += (cls == 0);
        }
    }
    sp[t] = pc; sn[t] = nc;
    __syncthreads();
    for (int s = 128; s > 0; s >>= 1) {
        if (t < s) { sp[t] += sp[t + s]; sn[t] += sn[t + s]; }
        __syncthreads();
    }
    if (t == 0) {
        g_posCnt[bid] = sp[0];
        g_negCnt[bid] = sn[0];
        __threadfence();
        atomicAdd(&g_done1, 1);
    }

    // ---- grid sync 1: wait for all counts ----
    if (t == 0) {
        while (atomicAdd(&g_done1, 0) < nb) __nanosleep(64);
    }
    __syncthreads();
    __threadfence();

    // ---- phase 2: block prefix over earlier blocks, then ordered scatter ----
    sp[t] = (t < bid) ? g_posCnt[t] : 0;
    sn[t] = (t < bid) ? g_negCnt[t] : 0;
    __syncthreads();
    for (int s = 128; s > 0; s >>= 1) {
        if (t < s) { sp[t] += sp[t + s]; sn[t] += sn[t + s]; }
        __syncthreads();
    }
    if (t == 0) { s_b0 = sp[0]; s_b1 = sn[0]; }
    __syncthreads();
    int posBase = s_b0, negBase = s_b1;

    if (posBase < LIST_CAP || negBase < LIST_CAP) {
        __syncthreads();
        sp[t] = pc; sn[t] = nc;       // intra-block inclusive scan
        __syncthreads();
        for (int off = 1; off < 256; off <<= 1) {
            int vp = (t >= off) ? sp[t - off] : 0;
            int vn = (t >= off) ? sn[t - off] : 0;
            __syncthreads();
            sp[t] += vp; sn[t] += vn;
            __syncthreads();
        }
        int pr = posBase + sp[t] - pc;
        int nr = negBase + sn[t] - nc;
        #pragma unroll
        for (int j = 0; j < 8; j++) {
            int i = base + t * 8 + j;
            int cls = cl[j] & 3;
            unsigned packed = ((unsigned)i << 8) | cl[j];
            if (cls >= 2)      { if (pr < LIST_CAP) g_posList[pr] = packed; pr++; }
            else if (cls == 0) { if (nr < LIST_CAP) g_negList[nr] = packed; nr++; }
        }
    }
    __syncthreads();

    // ---- grid sync 2: last block to finish scatter runs the loss ----
    if (t == 0) {
        __threadfence();
        int old = atomicAdd(&g_done2, 1);
        s_flag = (old == nb - 1);
    }
    __syncthreads();
    if (!s_flag) return;
    __threadfence();

    // ---- phase 3: totals ----
    sp[t] = (t < nb) ? g_posCnt[t] : 0;
    sn[t] = (t < nb) ? g_negCnt[t] : 0;
    __syncthreads();
    for (int s = 128; s > 0; s >>= 1) {
        if (t < s) { sp[t] += sp[t + s]; sn[t] += sn[t + s]; }
        __syncthreads();
    }
    if (t == 0) { s_b0 = sp[0]; s_b1 = sn[0]; }
    __syncthreads();
    int posTotal = s_b0, negTotal = s_b1;

    bool bug = (posTotal >= LIST_CAP);
    int P = bug ? LIST_CAP : posTotal;                 // P <= 128
    int Nn = min(bug ? LIST_CAP : P, negTotal);        // Nn <= 128

    float cls = 0.f, reg = 0.f, ncls = 0.f;

    if (t < LIST_CAP) {
        // threads 0..127: one positive item each
        if (t < P) {
            unsigned e = g_posList[t];
            int idx = (int)(e >> 8);
            int gidx = (e >> 2) & 63;
            float4 a = anchors[idx];
            float lse, x0;
            if (bug) {
                float m = fmaxf(fmaxf(a.x, a.y), fmaxf(a.z, a.w));
                float s = expf(a.x-m) + expf(a.y-m) + expf(a.z-m) + expf(a.w-m);
                lse = m + logf(s); x0 = a.x;
            } else {
                float s0 = score[2 * idx], s1 = score[2 * idx + 1];
                float m = fmaxf(s0, s1);
                lse = m + logf(expf(s0 - m) + expf(s1 - m)); x0 = s0;
            }
            cls = lse - x0;

            float4 g = gts[gidx];
            float aw = a.z - a.x, ah = a.w - a.y;
            float acx = a.x + aw * 0.5f, acy = a.y + ah * 0.5f;
            float gw = g.z - g.x, gh = g.w - g.y;
            float gcx = g.x + gw * 0.5f, gcy = g.y + gh * 0.5f;
            float tx = (gcx - acx) / aw;
            float ty = (gcy - acy) / ah;
            float tw = logf(gw / aw);
            float th = logf(gh / ah);
            float4 r = regp[idx];
            float d, ad;
            d = r.x - tx; ad = fabsf(d); reg += (ad < 1.f) ? 0.5f*d*d : ad - 0.5f;
            d = r.y - ty; ad = fabsf(d); reg += (ad < 1.f) ? 0.5f*d*d : ad - 0.5f;
            d = r.z - tw; ad = fabsf(d); reg += (ad < 1.f) ? 0.5f*d*d : ad - 0.5f;
            d = r.w - th; ad = fabsf(d); reg += (ad < 1.f) ? 0.5f*d*d : ad - 0.5f;
        }
    } else {
        // threads 128..255: one negative item each
        int j = t - LIST_CAP;
        if (j < Nn) {
            int idx = (int)(g_negList[j] >> 8);
            float s0 = score[2 * idx], s1 = score[2 * idx + 1];
            float m = fmaxf(s0, s1);
            float lse = m + logf(expf(s0 - m) + expf(s1 - m));
            ncls = lse - s1;
        }
    }

    __shared__ float fc[256], fr[256], fn[256];
    fc[t] = cls; fr[t] = reg; fn[t] = ncls;
    __syncthreads();
    for (int s = 128; s > 0; s >>= 1) {
        if (t < s) { fc[t] += fc[t+s]; fr[t] += fr[t+s]; fn[t] += fn[t+s]; }
        __syncthreads();
    }
    if (t == 0) {
        float pcl = (P  > 0) ? fc[0] / (float)P  : 0.f;
        float rg  = (P  > 0) ? fr[0] / (float)P  : 0.f;
        float ncl = (Nn > 0) ? fn[0] / (float)Nn : 0.f;
        float v = pcl + rg + ncl;
        for (int o = 0; o < out_size; o++) out[o] = v;
        g_done1 = 0;
        g_done2 = 0;
    }
    if (t < MAXG) g_best[t] = 0ull;   // clean state for next graph replay
}

// ---------------- host launcher ---------------------------------------------
extern "C" void kernel_launch(void* const* d_in, const int* in_sizes, int n_in,
                              void* d_out, int out_size) {
    const float*  score   = (const float*)d_in[0];      // (A,2)
    const float4* regp    = (const float4*)d_in[1];     // (A,4)
    const float4* anchors = (const float4*)d_in[2];     // (A,4)
    const float4* gts     = (const float4*)d_in[3];     // (G,4)
    int A = in_sizes[0] / 2;
    int G = in_sizes[3] / 4;
    if (G > MAXG) G = MAXG;

    int grid1 = (A + 511) / 512;        // one anchor pair per thread (977)
    int nb = (A + CHUNK - 1) / CHUNK;   // 245 <= NB_MAX, all blocks co-resident

    k_iou<<<grid1, 256>>>(anchors, gts, A, G);
    k_post<<<nb, 256>>>(score, regp, anchors, gts, (float*)d_out, out_size,
                        A, G, nb);
}